// round 15
// baseline (speedup 1.0000x reference)
#include <cuda_runtime.h>
#include <cuda_bf16.h>
#include <cstdint>
#include <cstddef>

// Problem constants
#define NB   16
#define CIN  2048
#define MID  512
#define HW   1024
#define DQK  128
#define NHEAD 4
#define ATT_SCALE 0.08838834764831845f
#define BN_EPS 1e-5f

// bf16 GEMM tile: block 128(pos) x 128(ch), K-chunk 32 (16 bf16x2 rows),
// 8 warps of 32(pos)x64(ch), 4-stage cp.async
#define LDA2 136
#define A_ST2 (16 * LDA2)
#define B_ST2 2048
#define GEMM_SMEM ((4 * A_ST2 + 4 * B_ST2) * 4)   // 67584 B

// Flash (FA2-style, R11 config): x-tile 64, 128 threads, 4 warps of 16 x 128
#define QLD 36                       // Qs row stride (u32), conflict-free
#define CLD 136                      // ring row stride (u32)
#define CH_SZ (16 * CLD)             // 2176 u32 per K/V chunk
#define OLD 68                       // O transpose buffer stride

// Scratch (device globals — allocation-free kernel_launch)
__device__ uint32_t g_x2   [(size_t)NB * (CIN / 2) * HW];  // x bf16x2 [n][ch2][pos]
__device__ uint32_t g_out12[(size_t)NB * (MID / 2) * HW];  // out1 bf16x2
__device__ uint32_t g_qk2  [(size_t)NB * 512 * HW];        // q'/k' bf16x2 [n][d2][pos]
__device__ uint32_t g_v2   [(size_t)NB * 512 * 512];       // v bf16x2 [n][y2][ch]
__device__ uint32_t g_attn2[(size_t)NB * (MID / 2) * HW];  // attn bf16x2
__device__ uint32_t g_w1u  [(size_t)MID * CIN / 2];
__device__ uint32_t g_wqkvu[(size_t)1536 * MID / 2];
__device__ uint32_t g_w3u  [(size_t)CIN * MID / 2];

// ---------------------------------------------------------------------------
__device__ __forceinline__ uint32_t bfpack(float lo, float hi) {
    uint32_t r;
    asm("cvt.rn.bf16x2.f32 %0, %1, %2;" : "=r"(r) : "f"(hi), "f"(lo));
    return r;
}

__device__ __forceinline__ void cp16u(uint32_t* dst, const uint32_t* src) {
    uint32_t d = (uint32_t)__cvta_generic_to_shared(dst);
    asm volatile("cp.async.cg.shared.global [%0], [%1], 16;\n" :: "r"(d), "l"(src));
}
#define CP_COMMIT asm volatile("cp.async.commit_group;\n" ::: "memory")
#define CP_WAIT0  asm volatile("cp.async.wait_group 0;\n" ::: "memory")
#define CP_WAIT1  asm volatile("cp.async.wait_group 1;\n" ::: "memory")
#define CP_WAIT2  asm volatile("cp.async.wait_group 2;\n" ::: "memory")

#define MMA_BF16(acc4, a0, a1, a2, a3, b0, b1) \
    asm volatile( \
        "mma.sync.aligned.m16n8k16.row.col.f32.bf16.bf16.f32 " \
        "{%0,%1,%2,%3}, {%4,%5,%6,%7}, {%8,%9}, {%0,%1,%2,%3};\n" \
        : "+f"((acc4)[0]), "+f"((acc4)[1]), "+f"((acc4)[2]), "+f"((acc4)[3]) \
        : "r"(a0), "r"(a1), "r"(a2), "r"(a3), "r"(b0), "r"(b1))

// ---------------------------------------------------------------------------
// x -> bf16x2 pair layout [n][ch2][pos]
// ---------------------------------------------------------------------------
__global__ __launch_bounds__(256) void k_roundx(const float* __restrict__ x,
                                                uint32_t* __restrict__ dst) {
    size_t t = (size_t)blockIdx.x * 256 + threadIdx.x;
    int pos = (int)(t & (HW - 1));
    size_t c2n = t >> 10;
    size_t base = (size_t)2 * c2n * HW + pos;
    dst[t] = bfpack(x[base], x[base + HW]);
}

// ---------------------------------------------------------------------------
// Weight repack into bf16 B-fragment order for m16n8k16.
// ---------------------------------------------------------------------------
__global__ __launch_bounds__(256) void k_repackb(const float* __restrict__ src,
                                                 uint32_t* __restrict__ dst,
                                                 int Mout, int K) {
    size_t e = (size_t)blockIdx.x * 256 + threadIdx.x;
    if (e >= (size_t)Mout * K / 2) return;
    int comp = (int)(e & 3);
    int lane = (int)((e >> 2) & 31);
    int np   = (int)((e >> 7) & 3);
    int s    = (int)((e >> 9) & 1);
    int h    = (int)((e >> 10) & 1);
    size_t rest = e >> 11;
    int nch = K >> 5;
    int c = (int)(rest % nch);
    size_t tile = rest / nch;
    int grp = lane >> 2, tg = lane & 3;
    int nt = 2 * np + (comp >> 1);
    size_t n = tile * 128 + h * 64 + nt * 8 + grp;
    int kp = c * 16 + s * 8 + tg + (comp & 1) * 4;
    dst[e] = bfpack(src[n * K + 2 * kp], src[n * K + 2 * kp + 1]);
}

// ---------------------------------------------------------------------------
// bf16 GEMM MMA chunk (unchanged) + 4-stage mainloop
// ---------------------------------------------------------------------------
__device__ __forceinline__ void warp_mma_b(const uint32_t* sA, const uint32_t* sBh,
                                           float acc[2][8][4], int wm, int lane) {
    int grp = lane >> 2, tg = lane & 3;
#pragma unroll
    for (int s = 0; s < 2; s++) {
        uint32_t a[2][4];
#pragma unroll
        for (int mt = 0; mt < 2; mt++) {
            const uint32_t* ap = sA + (s * 8 + tg) * LDA2 + wm * 32 + mt * 16 + grp;
            a[mt][0] = ap[0];
            a[mt][1] = ap[8];
            a[mt][2] = ap[4 * LDA2];
            a[mt][3] = ap[4 * LDA2 + 8];
        }
#pragma unroll
        for (int np = 0; np < 4; np++) {
            uint4 bv = *(const uint4*)(sBh + (s * 4 + np) * 128 + lane * 4);
#pragma unroll
            for (int mt = 0; mt < 2; mt++)
                MMA_BF16(acc[mt][2 * np], a[mt][0], a[mt][1], a[mt][2], a[mt][3],
                         bv.x, bv.y);
#pragma unroll
            for (int mt = 0; mt < 2; mt++)
                MMA_BF16(acc[mt][2 * np + 1], a[mt][0], a[mt][1], a[mt][2], a[mt][3],
                         bv.z, bv.w);
        }
    }
}

__device__ __forceinline__ void gemm_loop(
    uint32_t* smp, const uint32_t* __restrict__ Aact,
    const uint32_t* __restrict__ Bw, int nchunks,
    float acc[2][8][4], int wm, int wh, int lane, int tid) {
    uint32_t* sA = smp;
    uint32_t* sB = smp + 4 * A_ST2;
    auto load_stage = [&](int c) {
        int st = c & 3;
        uint32_t* dA = sA + st * A_ST2;
        const uint32_t* srcA = Aact + (size_t)(c * 16) * HW;
#pragma unroll
        for (int i = 0; i < 2; i++) {
            int g = tid + i * 256, k = g >> 5, pq = (g & 31) * 4;
            cp16u(dA + k * LDA2 + pq, srcA + (size_t)k * HW + pq);
        }
        uint32_t* dB = sB + st * B_ST2;
        const uint32_t* srcB = Bw + (size_t)c * B_ST2;
#pragma unroll
        for (int i = 0; i < 2; i++)
            cp16u(dB + tid * 4 + i * 1024, srcB + tid * 4 + i * 1024);
        CP_COMMIT;
    };
    load_stage(0);
    load_stage(1);
    load_stage(2);
    for (int c = 0; c < nchunks; c++) {
        if (c == nchunks - 1)      { CP_WAIT0; }
        else if (c == nchunks - 2) { CP_WAIT1; }
        else                       { CP_WAIT2; }
        __syncthreads();
        if (c + 3 < nchunks) load_stage(c + 3);
        warp_mma_b(sA + (c & 3) * A_ST2, sB + (c & 3) * B_ST2 + wh * 1024,
                   acc, wm, lane);
    }
}

// ---------------------------------------------------------------------------
// GEMM1: out1 = bf16(relu(BN(x^T @ w1^T)))   K=2048.  grid (8, 4, NB)
// ---------------------------------------------------------------------------
__global__ __launch_bounds__(256, 2) void k_gemm1(
    const float* __restrict__ gamma, const float* __restrict__ beta,
    const float* __restrict__ mean, const float* __restrict__ var) {
    extern __shared__ uint32_t smp[];
    int n = blockIdx.z, p0 = blockIdx.x * 128, c0 = blockIdx.y * 128;
    int tid = threadIdx.x, lane = tid & 31, warp = tid >> 5;
    int wm = warp & 3, wh = warp >> 2;
    int grp = lane >> 2, tg = lane & 3;
    float acc[2][8][4] = {};
    gemm_loop(smp, g_x2 + (size_t)n * (CIN / 2) * HW + p0,
              g_w1u + (size_t)blockIdx.y * (CIN * 64), CIN / 32,
              acc, wm, wh, lane, tid);
    uint32_t* out2 = g_out12 + (size_t)n * (MID / 2) * HW;
#pragma unroll
    for (int nt = 0; nt < 8; nt++) {
        int ch = c0 + wh * 64 + nt * 8 + 2 * tg;
        float i0 = gamma[ch] * rsqrtf(var[ch] + BN_EPS);
        float b0 = beta[ch] - mean[ch] * i0;
        float i1 = gamma[ch + 1] * rsqrtf(var[ch + 1] + BN_EPS);
        float b1 = beta[ch + 1] - mean[ch + 1] * i1;
#pragma unroll
        for (int mt = 0; mt < 2; mt++) {
            int p = p0 + wm * 32 + mt * 16 + grp;
            float* a4 = acc[mt][nt];
            size_t row = (size_t)(ch >> 1) * HW;
            out2[row + p]     = bfpack(fmaxf(a4[0] * i0 + b0, 0.f),
                                       fmaxf(a4[1] * i1 + b1, 0.f));
            out2[row + p + 8] = bfpack(fmaxf(a4[2] * i0 + b0, 0.f),
                                       fmaxf(a4[3] * i1 + b1, 0.f));
        }
    }
}

// ---------------------------------------------------------------------------
// GEMM2: q'/k' -> g_qk2 (pairs along d); v -> g_v2 (pairs along y via shfl).
// grid (8, 12, NB)
// ---------------------------------------------------------------------------
__global__ __launch_bounds__(256, 2) void k_gemm2(
    const float* __restrict__ pos_h, const float* __restrict__ pos_w) {
    extern __shared__ uint32_t smp[];
    int n = blockIdx.z, p0 = blockIdx.x * 128, c0 = blockIdx.y * 128;
    int tid = threadIdx.x, lane = tid & 31, warp = tid >> 5;
    int wm = warp & 3, wh = warp >> 2;
    int grp = lane >> 2, tg = lane & 3;
    float acc[2][8][4] = {};
    gemm_loop(smp, g_out12 + (size_t)n * (MID / 2) * HW + p0,
              g_wqkvu + (size_t)blockIdx.y * (MID * 64), MID / 32,
              acc, wm, wh, lane, tid);
#pragma unroll
    for (int nt = 0; nt < 8; nt++) {
        int ch = c0 + wh * 64 + nt * 8 + 2 * tg;      // even
#pragma unroll
        for (int mt = 0; mt < 2; mt++) {
            int p = p0 + wm * 32 + mt * 16 + grp;
            float* a4 = acc[mt][nt];
            if (c0 < 512) {                          // q' pairs (d, d+1)
                uint32_t* q = g_qk2 + ((size_t)n * 512 + (ch >> 1)) * HW;
                q[p]     = bfpack(a4[0] * ATT_SCALE, a4[1] * ATT_SCALE);
                q[p + 8] = bfpack(a4[2] * ATT_SCALE, a4[3] * ATT_SCALE);
            } else if (c0 < 1024) {                  // k' = k + emb, pairs (d, d+1)
                int d0 = ch & 127, d1 = (ch + 1) & 127;
                uint32_t* q = g_qk2 + ((size_t)n * 512 + (ch >> 1)) * HW;
                int pa = p, pb = p + 8;
                float e00 = pos_h[(pa >> 5) * DQK + d0] + pos_w[(pa & 31) * DQK + d0];
                float e01 = pos_h[(pa >> 5) * DQK + d1] + pos_w[(pa & 31) * DQK + d1];
                float e10 = pos_h[(pb >> 5) * DQK + d0] + pos_w[(pb & 31) * DQK + d0];
                float e11 = pos_h[(pb >> 5) * DQK + d1] + pos_w[(pb & 31) * DQK + d1];
                q[pa] = bfpack(a4[0] + e00, a4[1] + e01);
                q[pb] = bfpack(a4[2] + e10, a4[3] + e11);
            } else {                                 // v -> g_v2 pairs along y
                int d = ch - 1024;                   // even
                float s0 = __shfl_xor_sync(0xffffffff, a4[0], 4);
                float s1 = __shfl_xor_sync(0xffffffff, a4[1], 4);
                float s2 = __shfl_xor_sync(0xffffffff, a4[2], 4);
                float s3 = __shfl_xor_sync(0xffffffff, a4[3], 4);
                if ((grp & 1) == 0) {
                    size_t y2a = (size_t)n * 512 + (p >> 1);
                    size_t y2b = (size_t)n * 512 + ((p + 8) >> 1);
                    *(uint2*)(g_v2 + y2a * 512 + d) =
                        make_uint2(bfpack(a4[0], s0), bfpack(a4[1], s1));
                    *(uint2*)(g_v2 + y2b * 512 + d) =
                        make_uint2(bfpack(a4[2], s2), bfpack(a4[3], s3));
                }
            }
        }
    }
}

// ---------------------------------------------------------------------------
// Flash attention FA2-style (exact R11 config): x-tile 64, 128 threads,
// 4 warps x (16 pos, 128 y), register softmax + P, 3-buffer cp.async ring.
// ---------------------------------------------------------------------------
__global__ __launch_bounds__(128) void k_flash() {
    __shared__ uint32_t smu[64 * QLD + 3 * CH_SZ];   // 8832 u32 = 34.5 KB
    uint32_t* Qs   = smu;                            // [64 x][QLD d2]
    uint32_t* ring = smu + 64 * QLD;                 // 3 x [16][CLD]
    uint32_t* Ob   = smu;                            // reused: [64 x][OLD d2]

    int z = blockIdx.z, n = z >> 2, head = z & 3;
    int x0 = blockIdx.x * 64;
    int tid = threadIdx.x, lane = tid & 31, warp = tid >> 5;
    int grp = lane >> 2, tg = lane & 3;
    int r0 = warp * 16 + grp;                        // warp-owned rows r0, r0+8

    const uint32_t* qp2 = g_qk2 + ((size_t)n * 512 + head * 64) * HW;   // [64 d2][1024 x]
    const uint32_t* kp2 = qp2 + (size_t)256 * HW;                       // [64 d2][1024 y]
    const uint32_t* v2p = g_v2 + (size_t)n * 512 * 512 + head * 128;    // [512 y2][512], slice

    auto load_chunk = [&](int t) {
        uint32_t* buf = ring + (t % 3) * CH_SZ;
        int j = t >> 3, ph = t & 7;
        const uint32_t* src;
        size_t ld;
        if (ph < 4) { src = kp2 + (size_t)(ph * 16) * HW + j * 128; ld = HW; }
        else        { src = v2p + (size_t)(j * 64 + (ph - 4) * 16) * 512; ld = 512; }
#pragma unroll
        for (int i = 0; i < 4; i++) {
            int g = tid + i * 128, k = g >> 5, cq = (g & 31) * 4;
            cp16u(buf + k * CLD + cq, src + (size_t)k * ld + cq);
        }
        CP_COMMIT;
    };

    load_chunk(0);
    load_chunk(1);

    // Q tile [64 x][64 d2], transposed from [d2][x]
#pragma unroll
    for (int i = 0; i < 8; i++) {
        int g = tid + i * 128;                // 1024 uint4
        int d2 = g >> 4, xq = (g & 15) * 4;
        uint4 v = *(const uint4*)(qp2 + (size_t)d2 * HW + x0 + xq);
        Qs[(xq + 0) * QLD + d2] = v.x;
        Qs[(xq + 1) * QLD + d2] = v.y;
        Qs[(xq + 2) * QLD + d2] = v.z;
        Qs[(xq + 3) * QLD + d2] = v.w;
    }
    float m0 = -1e30f, m1 = -1e30f, l0 = 0.f, l1 = 0.f;
    float acc_s[16][4] = {};
    float acc_o[16][4] = {};
    __syncthreads();

    for (int j = 0; j < 8; j++) {
        // ---- S = Q @ K'^T : 4 chunks of d32 ----
        for (int c = 0; c < 4; c++) {
            int t = j * 8 + c;
            if (t == 63) { CP_WAIT0; } else { CP_WAIT1; }
            __syncthreads();
            if (t + 2 < 64) load_chunk(t + 2);
            const uint32_t* B = ring + (t % 3) * CH_SZ;
#pragma unroll
            for (int sub = 0; sub < 2; sub++) {
                const uint32_t* ap = Qs + r0 * QLD + c * 16 + sub * 8 + tg;
                uint32_t a0 = ap[0];
                uint32_t a1 = ap[8 * QLD];
                uint32_t a2 = ap[4];
                uint32_t a3 = ap[8 * QLD + 4];
#pragma unroll
                for (int nt = 0; nt < 16; nt++) {
                    uint32_t b0 = B[(sub * 8 + tg) * CLD + nt * 8 + grp];
                    uint32_t b1 = B[(sub * 8 + 4 + tg) * CLD + nt * 8 + grp];
                    MMA_BF16(acc_s[nt], a0, a1, a2, a3, b0, b1);
                }
            }
        }
        // ---- warp-local online softmax (rows r0, r0+8) ----
        {
            float ml0 = -1e30f, ml1 = -1e30f;
#pragma unroll
            for (int nt = 0; nt < 16; nt++) {
                ml0 = fmaxf(ml0, fmaxf(acc_s[nt][0], acc_s[nt][1]));
                ml1 = fmaxf(ml1, fmaxf(acc_s[nt][2], acc_s[nt][3]));
            }
            ml0 = fmaxf(ml0, __shfl_xor_sync(0xffffffff, ml0, 1));
            ml0 = fmaxf(ml0, __shfl_xor_sync(0xffffffff, ml0, 2));
            ml1 = fmaxf(ml1, __shfl_xor_sync(0xffffffff, ml1, 1));
            ml1 = fmaxf(ml1, __shfl_xor_sync(0xffffffff, ml1, 2));
            float mn0 = fmaxf(m0, ml0), mn1 = fmaxf(m1, ml1);
            float sc0 = __expf(m0 - mn0), sc1 = __expf(m1 - mn1);
            m0 = mn0; m1 = mn1;
            float s0 = 0.f, s1 = 0.f;
#pragma unroll
            for (int nt = 0; nt < 16; nt++) {
                float e0 = __expf(acc_s[nt][0] - mn0);
                float e1 = __expf(acc_s[nt][1] - mn0);
                float e2 = __expf(acc_s[nt][2] - mn1);
                float e3 = __expf(acc_s[nt][3] - mn1);
                acc_s[nt][0] = e0; acc_s[nt][1] = e1;
                acc_s[nt][2] = e2; acc_s[nt][3] = e3;
                s0 += e0 + e1; s1 += e2 + e3;
            }
            s0 += __shfl_xor_sync(0xffffffff, s0, 1);
            s0 += __shfl_xor_sync(0xffffffff, s0, 2);
            s1 += __shfl_xor_sync(0xffffffff, s1, 1);
            s1 += __shfl_xor_sync(0xffffffff, s1, 2);
            l0 = l0 * sc0 + s0;
            l1 = l1 * sc1 + s1;
#pragma unroll
            for (int nt = 0; nt < 16; nt++) {
                acc_o[nt][0] *= sc0; acc_o[nt][1] *= sc0;
                acc_o[nt][2] *= sc1; acc_o[nt][3] *= sc1;
            }
        }
        // ---- O += P @ V : 4 chunks of y32, P packed from registers ----
        for (int c = 0; c < 4; c++) {
            int t = j * 8 + 4 + c;
            if (t == 63) { CP_WAIT0; } else { CP_WAIT1; }
            __syncthreads();
            if (t + 2 < 64) load_chunk(t + 2);
            const uint32_t* B = ring + (t % 3) * CH_SZ;
#pragma unroll
            for (int sub = 0; sub < 2; sub++) {
                int qp = c * 2 + sub;                // 16-y group index 0..7
                uint32_t a0 = bfpack(acc_s[2 * qp][0],     acc_s[2 * qp][1]);
                uint32_t a1 = bfpack(acc_s[2 * qp][2],     acc_s[2 * qp][3]);
                uint32_t a2 = bfpack(acc_s[2 * qp + 1][0], acc_s[2 * qp + 1][1]);
                uint32_t a3 = bfpack(acc_s[2 * qp + 1][2], acc_s[2 * qp + 1][3]);
#pragma unroll
                for (int nt = 0; nt < 16; nt++) {
                    uint32_t b0 = B[(sub * 8 + tg) * CLD + nt * 8 + grp];
                    uint32_t b1 = B[(sub * 8 + 4 + tg) * CLD + nt * 8 + grp];
                    MMA_BF16(acc_o[nt], a0, a1, a2, a3, b0, b1);
                }
            }
        }
    }

    // ---- epilogue: O /= l, relu, pack along d, smem transpose, store ----
    float inv0 = 1.f / l0, inv1 = 1.f / l1;
    __syncthreads();                                 // done with Qs/ring
#pragma unroll
    for (int nt = 0; nt < 16; nt++) {
        int d2 = nt * 4 + tg;
        Ob[r0 * OLD + d2] = bfpack(fmaxf(acc_o[nt][0] * inv0, 0.f),
                                   fmaxf(acc_o[nt][1] * inv0, 0.f));
        Ob[(r0 + 8) * OLD + d2] = bfpack(fmaxf(acc_o[nt][2] * inv1, 0.f),
                                         fmaxf(acc_o[nt][3] * inv1, 0.f));
    }
    __syncthreads();
    uint32_t* op2 = g_attn2 + ((size_t)n * (MID / 2) + head * (DQK / 2)) * HW;
#pragma unroll
    for (int i = 0; i < 32; i++) {
        int g = tid + i * 128;               // 4096 = 64 d2 * 64 x
        int d2 = g >> 6, xo = g & 63;
        op2[(size_t)d2 * HW + x0 + xo] = Ob[xo * OLD + d2];
    }
}

// ---------------------------------------------------------------------------
// GEMM3: out[ch][pos] = relu(BN(attn^T @ w3^T) + x)   grid (8, 16, NB)
// ---------------------------------------------------------------------------
__global__ __launch_bounds__(256, 2) void k_gemm3(
    const float* __restrict__ gamma, const float* __restrict__ beta,
    const float* __restrict__ mean, const float* __restrict__ var,
    const float* __restrict__ x, float* __restrict__ out) {
    extern __shared__ uint32_t smp[];
    int n = blockIdx.z, p0 = blockIdx.x * 128, c0 = blockIdx.y * 128;
    int tid = threadIdx.x, lane = tid & 31, warp = tid >> 5;
    int wm = warp & 3, wh = warp >> 2;
    int grp = lane >> 2, tg = lane & 3;
    float acc[2][8][4] = {};
    gemm_loop(smp, g_attn2 + (size_t)n * (MID / 2) * HW + p0,
              g_w3u + (size_t)blockIdx.y * (MID * 64), MID / 32,
              acc, wm, wh, lane, tid);
#pragma unroll
    for (int nt = 0; nt < 8; nt++) {
        int ch = c0 + wh * 64 + nt * 8 + 2 * tg;
        float i0 = gamma[ch] * rsqrtf(var[ch] + BN_EPS);
        float b0 = beta[ch] - mean[ch] * i0;
        float i1 = gamma[ch + 1] * rsqrtf(var[ch + 1] + BN_EPS);
        float b1 = beta[ch + 1] - mean[ch + 1] * i1;
#pragma unroll
        for (int mt = 0; mt < 2; mt++) {
            int p = p0 + wm * 32 + mt * 16 + grp;
            float* a4 = acc[mt][nt];
            size_t e0 = (size_t)n * CIN * HW + (size_t)ch * HW + p;
            size_t e1 = e0 + HW;
            out[e0]     = fmaxf(a4[0] * i0 + b0 + x[e0], 0.f);
            out[e1]     = fmaxf(a4[1] * i1 + b1 + x[e1], 0.f);
            out[e0 + 8] = fmaxf(a4[2] * i0 + b0 + x[e0 + 8], 0.f);
            out[e1 + 8] = fmaxf(a4[3] * i1 + b1 + x[e1 + 8], 0.f);
        }
    }
}

// ---------------------------------------------------------------------------
extern "C" void kernel_launch(void* const* d_in, const int* in_sizes, int n_in,
                              void* d_out, int out_size) {
    const float* x       = (const float*)d_in[0];
    const float* conv1_w = (const float*)d_in[1];
    const float* gamma1  = (const float*)d_in[2];
    const float* beta1   = (const float*)d_in[3];
    const float* mean1   = (const float*)d_in[4];
    const float* var1    = (const float*)d_in[5];
    const float* qk_w    = (const float*)d_in[6];
    const float* v_w     = (const float*)d_in[7];
    const float* pos_h   = (const float*)d_in[8];
    const float* pos_w   = (const float*)d_in[9];
    const float* conv3_w = (const float*)d_in[10];
    const float* gamma3  = (const float*)d_in[11];
    const float* beta3   = (const float*)d_in[12];
    const float* mean3   = (const float*)d_in[13];
    const float* var3    = (const float*)d_in[14];
    float* out = (float*)d_out;

    cudaFuncSetAttribute(k_gemm1, cudaFuncAttributeMaxDynamicSharedMemorySize,
                         GEMM_SMEM);
    cudaFuncSetAttribute(k_gemm2, cudaFuncAttributeMaxDynamicSharedMemorySize,
                         GEMM_SMEM);
    cudaFuncSetAttribute(k_gemm3, cudaFuncAttributeMaxDynamicSharedMemorySize,
                         GEMM_SMEM);

    uint32_t *p_x2, *p_w1, *p_wqkv, *p_w3;
    cudaGetSymbolAddress((void**)&p_x2, g_x2);
    cudaGetSymbolAddress((void**)&p_w1, g_w1u);
    cudaGetSymbolAddress((void**)&p_wqkv, g_wqkvu);
    cudaGetSymbolAddress((void**)&p_w3, g_w3u);

    dim3 blk256(256);
    {
        size_t nt = (size_t)NB * (CIN / 2) * HW;
        k_roundx<<<(unsigned)(nt / 256), blk256>>>(x, p_x2);
    }
    k_repackb<<<(MID * CIN / 2 + 255) / 256, blk256>>>(conv1_w, p_w1, MID, CIN);
    k_repackb<<<(1024 * MID / 2 + 255) / 256, blk256>>>(qk_w, p_wqkv, 1024, MID);
    k_repackb<<<(512 * MID / 2 + 255) / 256, blk256>>>(v_w,
                                                       p_wqkv + (size_t)1024 * MID / 2,
                                                       512, MID);
    k_repackb<<<(CIN * MID / 2 + 255) / 256, blk256>>>(conv3_w, p_w3, CIN, MID);

    k_gemm1<<<dim3(8, 4, NB), blk256, GEMM_SMEM>>>(gamma1, beta1, mean1, var1);
    k_gemm2<<<dim3(8, 12, NB), blk256, GEMM_SMEM>>>(pos_h, pos_w);
    k_flash<<<dim3(16, 1, NB * NHEAD), dim3(128)>>>();
    k_gemm3<<<dim3(8, 16, NB), blk256, GEMM_SMEM>>>(gamma3, beta3, mean3, var3, x, out);
}

// round 16
// speedup vs baseline: 1.5190x; 1.5190x over previous
#include <cuda_runtime.h>
#include <cuda_bf16.h>
#include <cstdint>
#include <cstddef>

// Problem constants
#define NB   16
#define CIN  2048
#define MID  512
#define HW   1024
#define DQK  128
#define NHEAD 4
#define ATT_SCALE 0.08838834764831845f
#define BN_EPS 1e-5f

// bf16 GEMM tile: block 128(pos) x 128(ch), K-chunk 32 (16 bf16x2 rows),
// 8 warps of 32(pos)x64(ch), 3-stage cp.async
#define LDA2 136
#define A_ST2 (16 * LDA2)
#define B_ST2 2048
#define GEMM_SMEM ((3 * A_ST2 + 3 * B_ST2) * 4)   // 50688 B

// Flash (FA2-style): x-tile 64, 128 threads, 4 warps of 16(pos) x 128(y)
#define QLD 36                       // Qs row stride (u32), conflict-free
#define CLD 136                      // ring row stride (u32)
#define CH_SZ (16 * CLD)             // 2176 u32 per K/V chunk
#define OLD 68                       // O transpose buffer stride

// Scratch (device globals — allocation-free kernel_launch)
__device__ uint32_t g_x2   [(size_t)NB * (CIN / 2) * HW];  // x bf16x2 [n][ch2][pos]
__device__ uint32_t g_out12[(size_t)NB * (MID / 2) * HW];  // out1 bf16x2
__device__ uint32_t g_qk2  [(size_t)NB * 512 * HW];        // q'/k' bf16x2 [n][d2][pos]
__device__ uint32_t g_v2   [(size_t)NB * 512 * 512];       // v bf16x2 [n][y2][ch]
__device__ uint32_t g_attn2[(size_t)NB * (MID / 2) * HW];  // attn bf16x2
__device__ uint32_t g_w1u  [(size_t)MID * CIN / 2];
__device__ uint32_t g_wqkvu[(size_t)1536 * MID / 2];
__device__ uint32_t g_w3u  [(size_t)CIN * MID / 2];

// ---------------------------------------------------------------------------
__device__ __forceinline__ uint32_t bfpack(float lo, float hi) {
    uint32_t r;
    asm("cvt.rn.bf16x2.f32 %0, %1, %2;" : "=r"(r) : "f"(hi), "f"(lo));
    return r;
}

__device__ __forceinline__ void cp16u(uint32_t* dst, const uint32_t* src) {
    uint32_t d = (uint32_t)__cvta_generic_to_shared(dst);
    asm volatile("cp.async.cg.shared.global [%0], [%1], 16;\n" :: "r"(d), "l"(src));
}
#define CP_COMMIT asm volatile("cp.async.commit_group;\n" ::: "memory")
#define CP_WAIT0  asm volatile("cp.async.wait_group 0;\n" ::: "memory")
#define CP_WAIT1  asm volatile("cp.async.wait_group 1;\n" ::: "memory")

#define MMA_BF16(acc4, a0, a1, a2, a3, b0, b1) \
    asm volatile( \
        "mma.sync.aligned.m16n8k16.row.col.f32.bf16.bf16.f32 " \
        "{%0,%1,%2,%3}, {%4,%5,%6,%7}, {%8,%9}, {%0,%1,%2,%3};\n" \
        : "+f"((acc4)[0]), "+f"((acc4)[1]), "+f"((acc4)[2]), "+f"((acc4)[3]) \
        : "r"(a0), "r"(a1), "r"(a2), "r"(a3), "r"(b0), "r"(b1))

// ---------------------------------------------------------------------------
// x -> bf16x2 pair layout [n][ch2][pos]
// ---------------------------------------------------------------------------
__global__ __launch_bounds__(256) void k_roundx(const float* __restrict__ x,
                                                uint32_t* __restrict__ dst) {
    size_t t = (size_t)blockIdx.x * 256 + threadIdx.x;
    int pos = (int)(t & (HW - 1));
    size_t c2n = t >> 10;
    size_t base = (size_t)2 * c2n * HW + pos;
    dst[t] = bfpack(x[base], x[base + HW]);
}

// ---------------------------------------------------------------------------
// Merged weight repack: all four weights in one launch.
// Per-element math identical to the per-weight version.
// Segments (u32 elements): w1 524288 | qk 262144 | v 131072 | w3 524288.
// ---------------------------------------------------------------------------
__global__ __launch_bounds__(256) void k_repack_all(
    const float* __restrict__ w1, const float* __restrict__ qkw,
    const float* __restrict__ vw, const float* __restrict__ w3,
    uint32_t* __restrict__ d1, uint32_t* __restrict__ dqkv,
    uint32_t* __restrict__ d3) {
    size_t e = (size_t)blockIdx.x * 256 + threadIdx.x;
    const float* src;
    uint32_t* dst;
    int K;
    size_t le;
    if (e < 524288)       { src = w1;  dst = d1;            K = 2048; le = e; }
    else if (e < 786432)  { src = qkw; dst = dqkv;          K = 512;  le = e - 524288; }
    else if (e < 917504)  { src = vw;  dst = dqkv + 262144; K = 512;  le = e - 786432; }
    else if (e < 1441792) { src = w3;  dst = d3;            K = 512;  le = e - 917504; }
    else return;
    int comp = (int)(le & 3);
    int lane = (int)((le >> 2) & 31);
    int np   = (int)((le >> 7) & 3);
    int s    = (int)((le >> 9) & 1);
    int h    = (int)((le >> 10) & 1);
    size_t rest = le >> 11;
    int nch = K >> 5;
    int c = (int)(rest % nch);
    size_t tile = rest / nch;
    int grp = lane >> 2, tg = lane & 3;
    int nt = 2 * np + (comp >> 1);
    size_t n = tile * 128 + h * 64 + nt * 8 + grp;
    int kp = c * 16 + s * 8 + tg + (comp & 1) * 4;
    dst[le] = bfpack(src[n * K + 2 * kp], src[n * K + 2 * kp + 1]);
}

// ---------------------------------------------------------------------------
// bf16 GEMM MMA chunk + 3-stage mainloop (exact R11)
// ---------------------------------------------------------------------------
__device__ __forceinline__ void warp_mma_b(const uint32_t* sA, const uint32_t* sBh,
                                           float acc[2][8][4], int wm, int lane) {
    int grp = lane >> 2, tg = lane & 3;
#pragma unroll
    for (int s = 0; s < 2; s++) {
        uint32_t a[2][4];
#pragma unroll
        for (int mt = 0; mt < 2; mt++) {
            const uint32_t* ap = sA + (s * 8 + tg) * LDA2 + wm * 32 + mt * 16 + grp;
            a[mt][0] = ap[0];
            a[mt][1] = ap[8];
            a[mt][2] = ap[4 * LDA2];
            a[mt][3] = ap[4 * LDA2 + 8];
        }
#pragma unroll
        for (int np = 0; np < 4; np++) {
            uint4 bv = *(const uint4*)(sBh + (s * 4 + np) * 128 + lane * 4);
#pragma unroll
            for (int mt = 0; mt < 2; mt++)
                MMA_BF16(acc[mt][2 * np], a[mt][0], a[mt][1], a[mt][2], a[mt][3],
                         bv.x, bv.y);
#pragma unroll
            for (int mt = 0; mt < 2; mt++)
                MMA_BF16(acc[mt][2 * np + 1], a[mt][0], a[mt][1], a[mt][2], a[mt][3],
                         bv.z, bv.w);
        }
    }
}

__device__ __forceinline__ void gemm_loop(
    uint32_t* smp, const uint32_t* __restrict__ Aact,
    const uint32_t* __restrict__ Bw, int nchunks,
    float acc[2][8][4], int wm, int wh, int lane, int tid) {
    uint32_t* sA = smp;
    uint32_t* sB = smp + 3 * A_ST2;
    auto load_stage = [&](int c) {
        int st = c % 3;
        uint32_t* dA = sA + st * A_ST2;
        const uint32_t* srcA = Aact + (size_t)(c * 16) * HW;
#pragma unroll
        for (int i = 0; i < 2; i++) {
            int g = tid + i * 256, k = g >> 5, pq = (g & 31) * 4;
            cp16u(dA + k * LDA2 + pq, srcA + (size_t)k * HW + pq);
        }
        uint32_t* dB = sB + st * B_ST2;
        const uint32_t* srcB = Bw + (size_t)c * B_ST2;
#pragma unroll
        for (int i = 0; i < 2; i++)
            cp16u(dB + tid * 4 + i * 1024, srcB + tid * 4 + i * 1024);
        CP_COMMIT;
    };
    load_stage(0);
    load_stage(1);
    for (int c = 0; c < nchunks; c++) {
        if (c == nchunks - 1) { CP_WAIT0; } else { CP_WAIT1; }
        __syncthreads();
        if (c + 2 < nchunks) load_stage(c + 2);
        warp_mma_b(sA + (c % 3) * A_ST2, sB + (c % 3) * B_ST2 + wh * 1024,
                   acc, wm, lane);
    }
}

// ---------------------------------------------------------------------------
// GEMM1: out1 = bf16(relu(BN(x^T @ w1^T)))   K=2048.  grid (8, 4, NB)
// ---------------------------------------------------------------------------
__global__ __launch_bounds__(256, 2) void k_gemm1(
    const float* __restrict__ gamma, const float* __restrict__ beta,
    const float* __restrict__ mean, const float* __restrict__ var) {
    extern __shared__ uint32_t smp[];
    int n = blockIdx.z, p0 = blockIdx.x * 128, c0 = blockIdx.y * 128;
    int tid = threadIdx.x, lane = tid & 31, warp = tid >> 5;
    int wm = warp & 3, wh = warp >> 2;
    int grp = lane >> 2, tg = lane & 3;
    float acc[2][8][4] = {};
    gemm_loop(smp, g_x2 + (size_t)n * (CIN / 2) * HW + p0,
              g_w1u + (size_t)blockIdx.y * (CIN * 64), CIN / 32,
              acc, wm, wh, lane, tid);
    uint32_t* out2 = g_out12 + (size_t)n * (MID / 2) * HW;
#pragma unroll
    for (int nt = 0; nt < 8; nt++) {
        int ch = c0 + wh * 64 + nt * 8 + 2 * tg;
        float i0 = gamma[ch] * rsqrtf(var[ch] + BN_EPS);
        float b0 = beta[ch] - mean[ch] * i0;
        float i1 = gamma[ch + 1] * rsqrtf(var[ch + 1] + BN_EPS);
        float b1 = beta[ch + 1] - mean[ch + 1] * i1;
#pragma unroll
        for (int mt = 0; mt < 2; mt++) {
            int p = p0 + wm * 32 + mt * 16 + grp;
            float* a4 = acc[mt][nt];
            size_t row = (size_t)(ch >> 1) * HW;
            out2[row + p]     = bfpack(fmaxf(a4[0] * i0 + b0, 0.f),
                                       fmaxf(a4[1] * i1 + b1, 0.f));
            out2[row + p + 8] = bfpack(fmaxf(a4[2] * i0 + b0, 0.f),
                                       fmaxf(a4[3] * i1 + b1, 0.f));
        }
    }
}

// ---------------------------------------------------------------------------
// GEMM2: q'/k' -> g_qk2 (pairs along d); v -> g_v2 (pairs along y via shfl).
// grid (8, 12, NB)
// ---------------------------------------------------------------------------
__global__ __launch_bounds__(256, 2) void k_gemm2(
    const float* __restrict__ pos_h, const float* __restrict__ pos_w) {
    extern __shared__ uint32_t smp[];
    int n = blockIdx.z, p0 = blockIdx.x * 128, c0 = blockIdx.y * 128;
    int tid = threadIdx.x, lane = tid & 31, warp = tid >> 5;
    int wm = warp & 3, wh = warp >> 2;
    int grp = lane >> 2, tg = lane & 3;
    float acc[2][8][4] = {};
    gemm_loop(smp, g_out12 + (size_t)n * (MID / 2) * HW + p0,
              g_wqkvu + (size_t)blockIdx.y * (MID * 64), MID / 32,
              acc, wm, wh, lane, tid);
#pragma unroll
    for (int nt = 0; nt < 8; nt++) {
        int ch = c0 + wh * 64 + nt * 8 + 2 * tg;      // even
#pragma unroll
        for (int mt = 0; mt < 2; mt++) {
            int p = p0 + wm * 32 + mt * 16 + grp;
            float* a4 = acc[mt][nt];
            if (c0 < 512) {                          // q' pairs (d, d+1)
                uint32_t* q = g_qk2 + ((size_t)n * 512 + (ch >> 1)) * HW;
                q[p]     = bfpack(a4[0] * ATT_SCALE, a4[1] * ATT_SCALE);
                q[p + 8] = bfpack(a4[2] * ATT_SCALE, a4[3] * ATT_SCALE);
            } else if (c0 < 1024) {                  // k' = k + emb, pairs (d, d+1)
                int d0 = ch & 127, d1 = (ch + 1) & 127;
                uint32_t* q = g_qk2 + ((size_t)n * 512 + (ch >> 1)) * HW;
                int pa = p, pb = p + 8;
                float e00 = pos_h[(pa >> 5) * DQK + d0] + pos_w[(pa & 31) * DQK + d0];
                float e01 = pos_h[(pa >> 5) * DQK + d1] + pos_w[(pa & 31) * DQK + d1];
                float e10 = pos_h[(pb >> 5) * DQK + d0] + pos_w[(pb & 31) * DQK + d0];
                float e11 = pos_h[(pb >> 5) * DQK + d1] + pos_w[(pb & 31) * DQK + d1];
                q[pa] = bfpack(a4[0] + e00, a4[1] + e01);
                q[pb] = bfpack(a4[2] + e10, a4[3] + e11);
            } else {                                 // v -> g_v2 pairs along y
                int d = ch - 1024;                   // even
                float s0 = __shfl_xor_sync(0xffffffff, a4[0], 4);
                float s1 = __shfl_xor_sync(0xffffffff, a4[1], 4);
                float s2 = __shfl_xor_sync(0xffffffff, a4[2], 4);
                float s3 = __shfl_xor_sync(0xffffffff, a4[3], 4);
                if ((grp & 1) == 0) {
                    size_t y2a = (size_t)n * 512 + (p >> 1);
                    size_t y2b = (size_t)n * 512 + ((p + 8) >> 1);
                    *(uint2*)(g_v2 + y2a * 512 + d) =
                        make_uint2(bfpack(a4[0], s0), bfpack(a4[1], s1));
                    *(uint2*)(g_v2 + y2b * 512 + d) =
                        make_uint2(bfpack(a4[2], s2), bfpack(a4[3], s3));
                }
            }
        }
    }
}

// ---------------------------------------------------------------------------
// Flash attention FA2-style (exact R11): x-tile 64, 128 threads,
// 4 warps x (16 pos, 128 y), register softmax + P, 3-buffer cp.async ring.
// ---------------------------------------------------------------------------
__global__ __launch_bounds__(128) void k_flash() {
    __shared__ uint32_t smu[64 * QLD + 3 * CH_SZ];   // 8832 u32 = 34.5 KB
    uint32_t* Qs   = smu;                            // [64 x][QLD d2]
    uint32_t* ring = smu + 64 * QLD;                 // 3 x [16][CLD]
    uint32_t* Ob   = smu;                            // reused: [64 x][OLD d2]

    int z = blockIdx.z, n = z >> 2, head = z & 3;
    int x0 = blockIdx.x * 64;
    int tid = threadIdx.x, lane = tid & 31, warp = tid >> 5;
    int grp = lane >> 2, tg = lane & 3;
    int r0 = warp * 16 + grp;                        // warp-owned rows r0, r0+8

    const uint32_t* qp2 = g_qk2 + ((size_t)n * 512 + head * 64) * HW;   // [64 d2][1024 x]
    const uint32_t* kp2 = qp2 + (size_t)256 * HW;                       // [64 d2][1024 y]
    const uint32_t* v2p = g_v2 + (size_t)n * 512 * 512 + head * 128;    // [512 y2][512], slice

    auto load_chunk = [&](int t) {
        uint32_t* buf = ring + (t % 3) * CH_SZ;
        int j = t >> 3, ph = t & 7;
        const uint32_t* src;
        size_t ld;
        if (ph < 4) { src = kp2 + (size_t)(ph * 16) * HW + j * 128; ld = HW; }
        else        { src = v2p + (size_t)(j * 64 + (ph - 4) * 16) * 512; ld = 512; }
#pragma unroll
        for (int i = 0; i < 4; i++) {
            int g = tid + i * 128, k = g >> 5, cq = (g & 31) * 4;
            cp16u(buf + k * CLD + cq, src + (size_t)k * ld + cq);
        }
        CP_COMMIT;
    };

    load_chunk(0);
    load_chunk(1);

    // Q tile [64 x][64 d2], transposed from [d2][x]
#pragma unroll
    for (int i = 0; i < 8; i++) {
        int g = tid + i * 128;                // 1024 uint4
        int d2 = g >> 4, xq = (g & 15) * 4;
        uint4 v = *(const uint4*)(qp2 + (size_t)d2 * HW + x0 + xq);
        Qs[(xq + 0) * QLD + d2] = v.x;
        Qs[(xq + 1) * QLD + d2] = v.y;
        Qs[(xq + 2) * QLD + d2] = v.z;
        Qs[(xq + 3) * QLD + d2] = v.w;
    }
    float m0 = -1e30f, m1 = -1e30f, l0 = 0.f, l1 = 0.f;
    float acc_s[16][4] = {};
    float acc_o[16][4] = {};
    __syncthreads();

    for (int j = 0; j < 8; j++) {
        // ---- S = Q @ K'^T : 4 chunks of d32 ----
        for (int c = 0; c < 4; c++) {
            int t = j * 8 + c;
            if (t == 63) { CP_WAIT0; } else { CP_WAIT1; }
            __syncthreads();
            if (t + 2 < 64) load_chunk(t + 2);
            const uint32_t* B = ring + (t % 3) * CH_SZ;
#pragma unroll
            for (int sub = 0; sub < 2; sub++) {
                const uint32_t* ap = Qs + r0 * QLD + c * 16 + sub * 8 + tg;
                uint32_t a0 = ap[0];
                uint32_t a1 = ap[8 * QLD];
                uint32_t a2 = ap[4];
                uint32_t a3 = ap[8 * QLD + 4];
#pragma unroll
                for (int nt = 0; nt < 16; nt++) {
                    uint32_t b0 = B[(sub * 8 + tg) * CLD + nt * 8 + grp];
                    uint32_t b1 = B[(sub * 8 + 4 + tg) * CLD + nt * 8 + grp];
                    MMA_BF16(acc_s[nt], a0, a1, a2, a3, b0, b1);
                }
            }
        }
        // ---- warp-local online softmax (rows r0, r0+8) ----
        {
            float ml0 = -1e30f, ml1 = -1e30f;
#pragma unroll
            for (int nt = 0; nt < 16; nt++) {
                ml0 = fmaxf(ml0, fmaxf(acc_s[nt][0], acc_s[nt][1]));
                ml1 = fmaxf(ml1, fmaxf(acc_s[nt][2], acc_s[nt][3]));
            }
            ml0 = fmaxf(ml0, __shfl_xor_sync(0xffffffff, ml0, 1));
            ml0 = fmaxf(ml0, __shfl_xor_sync(0xffffffff, ml0, 2));
            ml1 = fmaxf(ml1, __shfl_xor_sync(0xffffffff, ml1, 1));
            ml1 = fmaxf(ml1, __shfl_xor_sync(0xffffffff, ml1, 2));
            float mn0 = fmaxf(m0, ml0), mn1 = fmaxf(m1, ml1);
            float sc0 = __expf(m0 - mn0), sc1 = __expf(m1 - mn1);
            m0 = mn0; m1 = mn1;
            float s0 = 0.f, s1 = 0.f;
#pragma unroll
            for (int nt = 0; nt < 16; nt++) {
                float e0 = __expf(acc_s[nt][0] - mn0);
                float e1 = __expf(acc_s[nt][1] - mn0);
                float e2 = __expf(acc_s[nt][2] - mn1);
                float e3 = __expf(acc_s[nt][3] - mn1);
                acc_s[nt][0] = e0; acc_s[nt][1] = e1;
                acc_s[nt][2] = e2; acc_s[nt][3] = e3;
                s0 += e0 + e1; s1 += e2 + e3;
            }
            s0 += __shfl_xor_sync(0xffffffff, s0, 1);
            s0 += __shfl_xor_sync(0xffffffff, s0, 2);
            s1 += __shfl_xor_sync(0xffffffff, s1, 1);
            s1 += __shfl_xor_sync(0xffffffff, s1, 2);
            l0 = l0 * sc0 + s0;
            l1 = l1 * sc1 + s1;
#pragma unroll
            for (int nt = 0; nt < 16; nt++) {
                acc_o[nt][0] *= sc0; acc_o[nt][1] *= sc0;
                acc_o[nt][2] *= sc1; acc_o[nt][3] *= sc1;
            }
        }
        // ---- O += P @ V : 4 chunks of y32, P packed from registers ----
        for (int c = 0; c < 4; c++) {
            int t = j * 8 + 4 + c;
            if (t == 63) { CP_WAIT0; } else { CP_WAIT1; }
            __syncthreads();
            if (t + 2 < 64) load_chunk(t + 2);
            const uint32_t* B = ring + (t % 3) * CH_SZ;
#pragma unroll
            for (int sub = 0; sub < 2; sub++) {
                int qp = c * 2 + sub;                // 16-y group index 0..7
                uint32_t a0 = bfpack(acc_s[2 * qp][0],     acc_s[2 * qp][1]);
                uint32_t a1 = bfpack(acc_s[2 * qp][2],     acc_s[2 * qp][3]);
                uint32_t a2 = bfpack(acc_s[2 * qp + 1][0], acc_s[2 * qp + 1][1]);
                uint32_t a3 = bfpack(acc_s[2 * qp + 1][2], acc_s[2 * qp + 1][3]);
#pragma unroll
                for (int nt = 0; nt < 16; nt++) {
                    uint32_t b0 = B[(sub * 8 + tg) * CLD + nt * 8 + grp];
                    uint32_t b1 = B[(sub * 8 + 4 + tg) * CLD + nt * 8 + grp];
                    MMA_BF16(acc_o[nt], a0, a1, a2, a3, b0, b1);
                }
            }
        }
    }

    // ---- epilogue: O /= l, relu, pack along d, smem transpose, store ----
    float inv0 = 1.f / l0, inv1 = 1.f / l1;
    __syncthreads();                                 // done with Qs/ring
#pragma unroll
    for (int nt = 0; nt < 16; nt++) {
        int d2 = nt * 4 + tg;
        Ob[r0 * OLD + d2] = bfpack(fmaxf(acc_o[nt][0] * inv0, 0.f),
                                   fmaxf(acc_o[nt][1] * inv0, 0.f));
        Ob[(r0 + 8) * OLD + d2] = bfpack(fmaxf(acc_o[nt][2] * inv1, 0.f),
                                         fmaxf(acc_o[nt][3] * inv1, 0.f));
    }
    __syncthreads();
    uint32_t* op2 = g_attn2 + ((size_t)n * (MID / 2) + head * (DQK / 2)) * HW;
#pragma unroll
    for (int i = 0; i < 32; i++) {
        int g = tid + i * 128;               // 4096 = 64 d2 * 64 x
        int d2 = g >> 6, xo = g & 63;
        op2[(size_t)d2 * HW + x0 + xo] = Ob[xo * OLD + d2];
    }
}

// ---------------------------------------------------------------------------
// GEMM3: out[ch][pos] = relu(BN(attn^T @ w3^T) + x)   grid (8, 16, NB)
// ---------------------------------------------------------------------------
__global__ __launch_bounds__(256, 2) void k_gemm3(
    const float* __restrict__ gamma, const float* __restrict__ beta,
    const float* __restrict__ mean, const float* __restrict__ var,
    const float* __restrict__ x, float* __restrict__ out) {
    extern __shared__ uint32_t smp[];
    int n = blockIdx.z, p0 = blockIdx.x * 128, c0 = blockIdx.y * 128;
    int tid = threadIdx.x, lane = tid & 31, warp = tid >> 5;
    int wm = warp & 3, wh = warp >> 2;
    int grp = lane >> 2, tg = lane & 3;
    float acc[2][8][4] = {};
    gemm_loop(smp, g_attn2 + (size_t)n * (MID / 2) * HW + p0,
              g_w3u + (size_t)blockIdx.y * (MID * 64), MID / 32,
              acc, wm, wh, lane, tid);
#pragma unroll
    for (int nt = 0; nt < 8; nt++) {
        int ch = c0 + wh * 64 + nt * 8 + 2 * tg;
        float i0 = gamma[ch] * rsqrtf(var[ch] + BN_EPS);
        float b0 = beta[ch] - mean[ch] * i0;
        float i1 = gamma[ch + 1] * rsqrtf(var[ch + 1] + BN_EPS);
        float b1 = beta[ch + 1] - mean[ch + 1] * i1;
#pragma unroll
        for (int mt = 0; mt < 2; mt++) {
            int p = p0 + wm * 32 + mt * 16 + grp;
            float* a4 = acc[mt][nt];
            size_t e0 = (size_t)n * CIN * HW + (size_t)ch * HW + p;
            size_t e1 = e0 + HW;
            out[e0]     = fmaxf(a4[0] * i0 + b0 + x[e0], 0.f);
            out[e1]     = fmaxf(a4[1] * i1 + b1 + x[e1], 0.f);
            out[e0 + 8] = fmaxf(a4[2] * i0 + b0 + x[e0 + 8], 0.f);
            out[e1 + 8] = fmaxf(a4[3] * i1 + b1 + x[e1 + 8], 0.f);
        }
    }
}

// ---------------------------------------------------------------------------
extern "C" void kernel_launch(void* const* d_in, const int* in_sizes, int n_in,
                              void* d_out, int out_size) {
    const float* x       = (const float*)d_in[0];
    const float* conv1_w = (const float*)d_in[1];
    const float* gamma1  = (const float*)d_in[2];
    const float* beta1   = (const float*)d_in[3];
    const float* mean1   = (const float*)d_in[4];
    const float* var1    = (const float*)d_in[5];
    const float* qk_w    = (const float*)d_in[6];
    const float* v_w     = (const float*)d_in[7];
    const float* pos_h   = (const float*)d_in[8];
    const float* pos_w   = (const float*)d_in[9];
    const float* conv3_w = (const float*)d_in[10];
    const float* gamma3  = (const float*)d_in[11];
    const float* beta3   = (const float*)d_in[12];
    const float* mean3   = (const float*)d_in[13];
    const float* var3    = (const float*)d_in[14];
    float* out = (float*)d_out;

    cudaFuncSetAttribute(k_gemm1, cudaFuncAttributeMaxDynamicSharedMemorySize,
                         GEMM_SMEM);
    cudaFuncSetAttribute(k_gemm2, cudaFuncAttributeMaxDynamicSharedMemorySize,
                         GEMM_SMEM);
    cudaFuncSetAttribute(k_gemm3, cudaFuncAttributeMaxDynamicSharedMemorySize,
                         GEMM_SMEM);

    uint32_t *p_x2, *p_w1, *p_wqkv, *p_w3;
    cudaGetSymbolAddress((void**)&p_x2, g_x2);
    cudaGetSymbolAddress((void**)&p_w1, g_w1u);
    cudaGetSymbolAddress((void**)&p_wqkv, g_wqkvu);
    cudaGetSymbolAddress((void**)&p_w3, g_w3u);

    dim3 blk256(256);
    {
        size_t nt = (size_t)NB * (CIN / 2) * HW;
        k_roundx<<<(unsigned)(nt / 256), blk256>>>(x, p_x2);
    }
    // all four weight repacks in one launch (1441792 u32 = 5632 blocks)
    k_repack_all<<<5632, blk256>>>(conv1_w, qk_w, v_w, conv3_w,
                                   p_w1, p_wqkv, p_w3);

    k_gemm1<<<dim3(8, 4, NB), blk256, GEMM_SMEM>>>(gamma1, beta1, mean1, var1);
    k_gemm2<<<dim3(8, 12, NB), blk256, GEMM_SMEM>>>(pos_h, pos_w);
    k_flash<<<dim3(16, 1, NB * NHEAD), dim3(128)>>>();
    k_gemm3<<<dim3(8, 16, NB), blk256, GEMM_SMEM>>>(gamma3, beta3, mean3, var3, x, out);
}

// round 17
// speedup vs baseline: 1.5865x; 1.0445x over previous
#include <cuda_runtime.h>
#include <cuda_bf16.h>
#include <cstdint>
#include <cstddef>

// Problem constants
#define NB   16
#define CIN  2048
#define MID  512
#define HW   1024
#define DQK  128
#define NHEAD 4
#define ATT_SCALE 0.08838834764831845f
#define BN_EPS 1e-5f

// bf16 GEMM tile: block 128(pos) x 128(ch), K-chunk 32 (16 bf16x2 rows),
// 8 warps of 32(pos)x64(ch), 3-stage cp.async
#define LDA2 136
#define A_ST2 (16 * LDA2)
#define B_ST2 2048
#define GEMM_SMEM ((3 * A_ST2 + 3 * B_ST2) * 4)   // 50688 B

// Flash (FA2-style): x-tile 64, 128 threads, 4 warps of 16(pos) x 128(y)
#define QLD 36                       // Qs row stride (u32), conflict-free
#define CLD 136                      // ring row stride (u32)
#define CH_SZ (16 * CLD)             // 2176 u32 per K/V chunk
#define OLD 68                       // O transpose buffer stride

// Scratch (device globals — allocation-free kernel_launch)
__device__ uint32_t g_x2   [(size_t)NB * (CIN / 2) * HW];  // x bf16x2 [n][ch2][pos]
__device__ uint32_t g_out12[(size_t)NB * (MID / 2) * HW];  // out1 bf16x2
__device__ uint32_t g_qk2  [(size_t)NB * 512 * HW];        // q'/k' bf16x2 [n][d2][pos]
__device__ uint32_t g_v2   [(size_t)NB * 512 * 512];       // v bf16x2 [n][y2][ch]
__device__ uint32_t g_attn2[(size_t)NB * (MID / 2) * HW];  // attn bf16x2
__device__ uint32_t g_w1u  [(size_t)MID * CIN / 2];
__device__ uint32_t g_wqkvu[(size_t)1536 * MID / 2];
__device__ uint32_t g_w3u  [(size_t)CIN * MID / 2];

// ---------------------------------------------------------------------------
__device__ __forceinline__ uint32_t bfpack(float lo, float hi) {
    uint32_t r;
    asm("cvt.rn.bf16x2.f32 %0, %1, %2;" : "=r"(r) : "f"(hi), "f"(lo));
    return r;
}

__device__ __forceinline__ void cp16u(uint32_t* dst, const uint32_t* src) {
    uint32_t d = (uint32_t)__cvta_generic_to_shared(dst);
    asm volatile("cp.async.cg.shared.global [%0], [%1], 16;\n" :: "r"(d), "l"(src));
}
#define CP_COMMIT asm volatile("cp.async.commit_group;\n" ::: "memory")
#define CP_WAIT0  asm volatile("cp.async.wait_group 0;\n" ::: "memory")
#define CP_WAIT1  asm volatile("cp.async.wait_group 1;\n" ::: "memory")

#define MMA_BF16(acc4, a0, a1, a2, a3, b0, b1) \
    asm volatile( \
        "mma.sync.aligned.m16n8k16.row.col.f32.bf16.bf16.f32 " \
        "{%0,%1,%2,%3}, {%4,%5,%6,%7}, {%8,%9}, {%0,%1,%2,%3};\n" \
        : "+f"((acc4)[0]), "+f"((acc4)[1]), "+f"((acc4)[2]), "+f"((acc4)[3]) \
        : "r"(a0), "r"(a1), "r"(a2), "r"(a3), "r"(b0), "r"(b1))

// ---------------------------------------------------------------------------
// x -> bf16x2 pair layout [n][ch2][pos], vectorized (uint4 per thread)
// ---------------------------------------------------------------------------
__global__ __launch_bounds__(256) void k_roundx(const float* __restrict__ x,
                                                uint4* __restrict__ dst) {
    size_t t = (size_t)blockIdx.x * 256 + threadIdx.x;   // uint4 index
    int pos4 = (int)(t & 255) * 4;                       // 256 uint4 per row
    size_t c2n = t >> 8;
    const float4 lo = *(const float4*)(x + (size_t)2 * c2n * HW + pos4);
    const float4 hi = *(const float4*)(x + ((size_t)2 * c2n + 1) * HW + pos4);
    dst[t] = make_uint4(bfpack(lo.x, hi.x), bfpack(lo.y, hi.y),
                        bfpack(lo.z, hi.z), bfpack(lo.w, hi.w));
}

// ---------------------------------------------------------------------------
// Merged weight repack: all four weights in one launch.
// Segments (u32 elements): w1 524288 | qk 262144 | v 131072 | w3 524288.
// ---------------------------------------------------------------------------
__global__ __launch_bounds__(256) void k_repack_all(
    const float* __restrict__ w1, const float* __restrict__ qkw,
    const float* __restrict__ vw, const float* __restrict__ w3,
    uint32_t* __restrict__ d1, uint32_t* __restrict__ dqkv,
    uint32_t* __restrict__ d3) {
    size_t e = (size_t)blockIdx.x * 256 + threadIdx.x;
    const float* src;
    uint32_t* dst;
    int K;
    size_t le;
    if (e < 524288)       { src = w1;  dst = d1;            K = 2048; le = e; }
    else if (e < 786432)  { src = qkw; dst = dqkv;          K = 512;  le = e - 524288; }
    else if (e < 917504)  { src = vw;  dst = dqkv + 262144; K = 512;  le = e - 786432; }
    else if (e < 1441792) { src = w3;  dst = d3;            K = 512;  le = e - 917504; }
    else return;
    int comp = (int)(le & 3);
    int lane = (int)((le >> 2) & 31);
    int np   = (int)((le >> 7) & 3);
    int s    = (int)((le >> 9) & 1);
    int h    = (int)((le >> 10) & 1);
    size_t rest = le >> 11;
    int nch = K >> 5;
    int c = (int)(rest % nch);
    size_t tile = rest / nch;
    int grp = lane >> 2, tg = lane & 3;
    int nt = 2 * np + (comp >> 1);
    size_t n = tile * 128 + h * 64 + nt * 8 + grp;
    int kp = c * 16 + s * 8 + tg + (comp & 1) * 4;
    dst[le] = bfpack(src[n * K + 2 * kp], src[n * K + 2 * kp + 1]);
}

// ---------------------------------------------------------------------------
// bf16 GEMM MMA chunk + 3-stage mainloop (exact R11/R15)
// ---------------------------------------------------------------------------
__device__ __forceinline__ void warp_mma_b(const uint32_t* sA, const uint32_t* sBh,
                                           float acc[2][8][4], int wm, int lane) {
    int grp = lane >> 2, tg = lane & 3;
#pragma unroll
    for (int s = 0; s < 2; s++) {
        uint32_t a[2][4];
#pragma unroll
        for (int mt = 0; mt < 2; mt++) {
            const uint32_t* ap = sA + (s * 8 + tg) * LDA2 + wm * 32 + mt * 16 + grp;
            a[mt][0] = ap[0];
            a[mt][1] = ap[8];
            a[mt][2] = ap[4 * LDA2];
            a[mt][3] = ap[4 * LDA2 + 8];
        }
#pragma unroll
        for (int np = 0; np < 4; np++) {
            uint4 bv = *(const uint4*)(sBh + (s * 4 + np) * 128 + lane * 4);
#pragma unroll
            for (int mt = 0; mt < 2; mt++)
                MMA_BF16(acc[mt][2 * np], a[mt][0], a[mt][1], a[mt][2], a[mt][3],
                         bv.x, bv.y);
#pragma unroll
            for (int mt = 0; mt < 2; mt++)
                MMA_BF16(acc[mt][2 * np + 1], a[mt][0], a[mt][1], a[mt][2], a[mt][3],
                         bv.z, bv.w);
        }
    }
}

__device__ __forceinline__ void gemm_loop(
    uint32_t* smp, const uint32_t* __restrict__ Aact,
    const uint32_t* __restrict__ Bw, int nchunks,
    float acc[2][8][4], int wm, int wh, int lane, int tid) {
    uint32_t* sA = smp;
    uint32_t* sB = smp + 3 * A_ST2;
    auto load_stage = [&](int c) {
        int st = c % 3;
        uint32_t* dA = sA + st * A_ST2;
        const uint32_t* srcA = Aact + (size_t)(c * 16) * HW;
#pragma unroll
        for (int i = 0; i < 2; i++) {
            int g = tid + i * 256, k = g >> 5, pq = (g & 31) * 4;
            cp16u(dA + k * LDA2 + pq, srcA + (size_t)k * HW + pq);
        }
        uint32_t* dB = sB + st * B_ST2;
        const uint32_t* srcB = Bw + (size_t)c * B_ST2;
#pragma unroll
        for (int i = 0; i < 2; i++)
            cp16u(dB + tid * 4 + i * 1024, srcB + tid * 4 + i * 1024);
        CP_COMMIT;
    };
    load_stage(0);
    load_stage(1);
    for (int c = 0; c < nchunks; c++) {
        if (c == nchunks - 1) { CP_WAIT0; } else { CP_WAIT1; }
        __syncthreads();
        if (c + 2 < nchunks) load_stage(c + 2);
        warp_mma_b(sA + (c % 3) * A_ST2, sB + (c % 3) * B_ST2 + wh * 1024,
                   acc, wm, lane);
    }
}

// ---------------------------------------------------------------------------
// GEMM1: out1 = bf16(relu(BN(x^T @ w1^T)))   K=2048.  grid (8, 4, NB)
// ---------------------------------------------------------------------------
__global__ __launch_bounds__(256, 2) void k_gemm1(
    const float* __restrict__ gamma, const float* __restrict__ beta,
    const float* __restrict__ mean, const float* __restrict__ var) {
    extern __shared__ uint32_t smp[];
    int n = blockIdx.z, p0 = blockIdx.x * 128, c0 = blockIdx.y * 128;
    int tid = threadIdx.x, lane = tid & 31, warp = tid >> 5;
    int wm = warp & 3, wh = warp >> 2;
    int grp = lane >> 2, tg = lane & 3;
    float acc[2][8][4] = {};
    gemm_loop(smp, g_x2 + (size_t)n * (CIN / 2) * HW + p0,
              g_w1u + (size_t)blockIdx.y * (CIN * 64), CIN / 32,
              acc, wm, wh, lane, tid);
    uint32_t* out2 = g_out12 + (size_t)n * (MID / 2) * HW;
#pragma unroll
    for (int nt = 0; nt < 8; nt++) {
        int ch = c0 + wh * 64 + nt * 8 + 2 * tg;
        float i0 = gamma[ch] * rsqrtf(var[ch] + BN_EPS);
        float b0 = beta[ch] - mean[ch] * i0;
        float i1 = gamma[ch + 1] * rsqrtf(var[ch + 1] + BN_EPS);
        float b1 = beta[ch + 1] - mean[ch + 1] * i1;
#pragma unroll
        for (int mt = 0; mt < 2; mt++) {
            int p = p0 + wm * 32 + mt * 16 + grp;
            float* a4 = acc[mt][nt];
            size_t row = (size_t)(ch >> 1) * HW;
            out2[row + p]     = bfpack(fmaxf(a4[0] * i0 + b0, 0.f),
                                       fmaxf(a4[1] * i1 + b1, 0.f));
            out2[row + p + 8] = bfpack(fmaxf(a4[2] * i0 + b0, 0.f),
                                       fmaxf(a4[3] * i1 + b1, 0.f));
        }
    }
}

// ---------------------------------------------------------------------------
// GEMM2: q'/k' -> g_qk2 (pairs along d); v -> g_v2 (pairs along y via shfl).
// grid (8, 12, NB)
// ---------------------------------------------------------------------------
__global__ __launch_bounds__(256, 2) void k_gemm2(
    const float* __restrict__ pos_h, const float* __restrict__ pos_w) {
    extern __shared__ uint32_t smp[];
    int n = blockIdx.z, p0 = blockIdx.x * 128, c0 = blockIdx.y * 128;
    int tid = threadIdx.x, lane = tid & 31, warp = tid >> 5;
    int wm = warp & 3, wh = warp >> 2;
    int grp = lane >> 2, tg = lane & 3;
    float acc[2][8][4] = {};
    gemm_loop(smp, g_out12 + (size_t)n * (MID / 2) * HW + p0,
              g_wqkvu + (size_t)blockIdx.y * (MID * 64), MID / 32,
              acc, wm, wh, lane, tid);
#pragma unroll
    for (int nt = 0; nt < 8; nt++) {
        int ch = c0 + wh * 64 + nt * 8 + 2 * tg;      // even
#pragma unroll
        for (int mt = 0; mt < 2; mt++) {
            int p = p0 + wm * 32 + mt * 16 + grp;
            float* a4 = acc[mt][nt];
            if (c0 < 512) {                          // q' pairs (d, d+1)
                uint32_t* q = g_qk2 + ((size_t)n * 512 + (ch >> 1)) * HW;
                q[p]     = bfpack(a4[0] * ATT_SCALE, a4[1] * ATT_SCALE);
                q[p + 8] = bfpack(a4[2] * ATT_SCALE, a4[3] * ATT_SCALE);
            } else if (c0 < 1024) {                  // k' = k + emb, pairs (d, d+1)
                int d0 = ch & 127, d1 = (ch + 1) & 127;
                uint32_t* q = g_qk2 + ((size_t)n * 512 + (ch >> 1)) * HW;
                int pa = p, pb = p + 8;
                float e00 = pos_h[(pa >> 5) * DQK + d0] + pos_w[(pa & 31) * DQK + d0];
                float e01 = pos_h[(pa >> 5) * DQK + d1] + pos_w[(pa & 31) * DQK + d1];
                float e10 = pos_h[(pb >> 5) * DQK + d0] + pos_w[(pb & 31) * DQK + d0];
                float e11 = pos_h[(pb >> 5) * DQK + d1] + pos_w[(pb & 31) * DQK + d1];
                q[pa] = bfpack(a4[0] + e00, a4[1] + e01);
                q[pb] = bfpack(a4[2] + e10, a4[3] + e11);
            } else {                                 // v -> g_v2 pairs along y
                int d = ch - 1024;                   // even
                float s0 = __shfl_xor_sync(0xffffffff, a4[0], 4);
                float s1 = __shfl_xor_sync(0xffffffff, a4[1], 4);
                float s2 = __shfl_xor_sync(0xffffffff, a4[2], 4);
                float s3 = __shfl_xor_sync(0xffffffff, a4[3], 4);
                if ((grp & 1) == 0) {
                    size_t y2a = (size_t)n * 512 + (p >> 1);
                    size_t y2b = (size_t)n * 512 + ((p + 8) >> 1);
                    *(uint2*)(g_v2 + y2a * 512 + d) =
                        make_uint2(bfpack(a4[0], s0), bfpack(a4[1], s1));
                    *(uint2*)(g_v2 + y2b * 512 + d) =
                        make_uint2(bfpack(a4[2], s2), bfpack(a4[3], s3));
                }
            }
        }
    }
}

// ---------------------------------------------------------------------------
// Flash attention FA2-style (exact R11): x-tile 64, 128 threads,
// 4 warps x (16 pos, 128 y), register softmax + P, 3-buffer cp.async ring.
// ---------------------------------------------------------------------------
__global__ __launch_bounds__(128) void k_flash() {
    __shared__ uint32_t smu[64 * QLD + 3 * CH_SZ];   // 8832 u32 = 34.5 KB
    uint32_t* Qs   = smu;                            // [64 x][QLD d2]
    uint32_t* ring = smu + 64 * QLD;                 // 3 x [16][CLD]
    uint32_t* Ob   = smu;                            // reused: [64 x][OLD d2]

    int z = blockIdx.z, n = z >> 2, head = z & 3;
    int x0 = blockIdx.x * 64;
    int tid = threadIdx.x, lane = tid & 31, warp = tid >> 5;
    int grp = lane >> 2, tg = lane & 3;
    int r0 = warp * 16 + grp;                        // warp-owned rows r0, r0+8

    const uint32_t* qp2 = g_qk2 + ((size_t)n * 512 + head * 64) * HW;   // [64 d2][1024 x]
    const uint32_t* kp2 = qp2 + (size_t)256 * HW;                       // [64 d2][1024 y]
    const uint32_t* v2p = g_v2 + (size_t)n * 512 * 512 + head * 128;    // [512 y2][512], slice

    auto load_chunk = [&](int t) {
        uint32_t* buf = ring + (t % 3) * CH_SZ;
        int j = t >> 3, ph = t & 7;
        const uint32_t* src;
        size_t ld;
        if (ph < 4) { src = kp2 + (size_t)(ph * 16) * HW + j * 128; ld = HW; }
        else        { src = v2p + (size_t)(j * 64 + (ph - 4) * 16) * 512; ld = 512; }
#pragma unroll
        for (int i = 0; i < 4; i++) {
            int g = tid + i * 128, k = g >> 5, cq = (g & 31) * 4;
            cp16u(buf + k * CLD + cq, src + (size_t)k * ld + cq);
        }
        CP_COMMIT;
    };

    load_chunk(0);
    load_chunk(1);

    // Q tile [64 x][64 d2], transposed from [d2][x]
#pragma unroll
    for (int i = 0; i < 8; i++) {
        int g = tid + i * 128;                // 1024 uint4
        int d2 = g >> 4, xq = (g & 15) * 4;
        uint4 v = *(const uint4*)(qp2 + (size_t)d2 * HW + x0 + xq);
        Qs[(xq + 0) * QLD + d2] = v.x;
        Qs[(xq + 1) * QLD + d2] = v.y;
        Qs[(xq + 2) * QLD + d2] = v.z;
        Qs[(xq + 3) * QLD + d2] = v.w;
    }
    float m0 = -1e30f, m1 = -1e30f, l0 = 0.f, l1 = 0.f;
    float acc_s[16][4] = {};
    float acc_o[16][4] = {};
    __syncthreads();

    for (int j = 0; j < 8; j++) {
        // ---- S = Q @ K'^T : 4 chunks of d32 ----
        for (int c = 0; c < 4; c++) {
            int t = j * 8 + c;
            if (t == 63) { CP_WAIT0; } else { CP_WAIT1; }
            __syncthreads();
            if (t + 2 < 64) load_chunk(t + 2);
            const uint32_t* B = ring + (t % 3) * CH_SZ;
#pragma unroll
            for (int sub = 0; sub < 2; sub++) {
                const uint32_t* ap = Qs + r0 * QLD + c * 16 + sub * 8 + tg;
                uint32_t a0 = ap[0];
                uint32_t a1 = ap[8 * QLD];
                uint32_t a2 = ap[4];
                uint32_t a3 = ap[8 * QLD + 4];
#pragma unroll
                for (int nt = 0; nt < 16; nt++) {
                    uint32_t b0 = B[(sub * 8 + tg) * CLD + nt * 8 + grp];
                    uint32_t b1 = B[(sub * 8 + 4 + tg) * CLD + nt * 8 + grp];
                    MMA_BF16(acc_s[nt], a0, a1, a2, a3, b0, b1);
                }
            }
        }
        // ---- warp-local online softmax (rows r0, r0+8) ----
        {
            float ml0 = -1e30f, ml1 = -1e30f;
#pragma unroll
            for (int nt = 0; nt < 16; nt++) {
                ml0 = fmaxf(ml0, fmaxf(acc_s[nt][0], acc_s[nt][1]));
                ml1 = fmaxf(ml1, fmaxf(acc_s[nt][2], acc_s[nt][3]));
            }
            ml0 = fmaxf(ml0, __shfl_xor_sync(0xffffffff, ml0, 1));
            ml0 = fmaxf(ml0, __shfl_xor_sync(0xffffffff, ml0, 2));
            ml1 = fmaxf(ml1, __shfl_xor_sync(0xffffffff, ml1, 1));
            ml1 = fmaxf(ml1, __shfl_xor_sync(0xffffffff, ml1, 2));
            float mn0 = fmaxf(m0, ml0), mn1 = fmaxf(m1, ml1);
            float sc0 = __expf(m0 - mn0), sc1 = __expf(m1 - mn1);
            m0 = mn0; m1 = mn1;
            float s0 = 0.f, s1 = 0.f;
#pragma unroll
            for (int nt = 0; nt < 16; nt++) {
                float e0 = __expf(acc_s[nt][0] - mn0);
                float e1 = __expf(acc_s[nt][1] - mn0);
                float e2 = __expf(acc_s[nt][2] - mn1);
                float e3 = __expf(acc_s[nt][3] - mn1);
                acc_s[nt][0] = e0; acc_s[nt][1] = e1;
                acc_s[nt][2] = e2; acc_s[nt][3] = e3;
                s0 += e0 + e1; s1 += e2 + e3;
            }
            s0 += __shfl_xor_sync(0xffffffff, s0, 1);
            s0 += __shfl_xor_sync(0xffffffff, s0, 2);
            s1 += __shfl_xor_sync(0xffffffff, s1, 1);
            s1 += __shfl_xor_sync(0xffffffff, s1, 2);
            l0 = l0 * sc0 + s0;
            l1 = l1 * sc1 + s1;
#pragma unroll
            for (int nt = 0; nt < 16; nt++) {
                acc_o[nt][0] *= sc0; acc_o[nt][1] *= sc0;
                acc_o[nt][2] *= sc1; acc_o[nt][3] *= sc1;
            }
        }
        // ---- O += P @ V : 4 chunks of y32, P packed from registers ----
        for (int c = 0; c < 4; c++) {
            int t = j * 8 + 4 + c;
            if (t == 63) { CP_WAIT0; } else { CP_WAIT1; }
            __syncthreads();
            if (t + 2 < 64) load_chunk(t + 2);
            const uint32_t* B = ring + (t % 3) * CH_SZ;
#pragma unroll
            for (int sub = 0; sub < 2; sub++) {
                int qp = c * 2 + sub;                // 16-y group index 0..7
                uint32_t a0 = bfpack(acc_s[2 * qp][0],     acc_s[2 * qp][1]);
                uint32_t a1 = bfpack(acc_s[2 * qp][2],     acc_s[2 * qp][3]);
                uint32_t a2 = bfpack(acc_s[2 * qp + 1][0], acc_s[2 * qp + 1][1]);
                uint32_t a3 = bfpack(acc_s[2 * qp + 1][2], acc_s[2 * qp + 1][3]);
#pragma unroll
                for (int nt = 0; nt < 16; nt++) {
                    uint32_t b0 = B[(sub * 8 + tg) * CLD + nt * 8 + grp];
                    uint32_t b1 = B[(sub * 8 + 4 + tg) * CLD + nt * 8 + grp];
                    MMA_BF16(acc_o[nt], a0, a1, a2, a3, b0, b1);
                }
            }
        }
    }

    // ---- epilogue: O /= l, relu, pack along d, smem transpose, store ----
    float inv0 = 1.f / l0, inv1 = 1.f / l1;
    __syncthreads();                                 // done with Qs/ring
#pragma unroll
    for (int nt = 0; nt < 16; nt++) {
        int d2 = nt * 4 + tg;
        Ob[r0 * OLD + d2] = bfpack(fmaxf(acc_o[nt][0] * inv0, 0.f),
                                   fmaxf(acc_o[nt][1] * inv0, 0.f));
        Ob[(r0 + 8) * OLD + d2] = bfpack(fmaxf(acc_o[nt][2] * inv1, 0.f),
                                         fmaxf(acc_o[nt][3] * inv1, 0.f));
    }
    __syncthreads();
    uint32_t* op2 = g_attn2 + ((size_t)n * (MID / 2) + head * (DQK / 2)) * HW;
#pragma unroll
    for (int i = 0; i < 32; i++) {
        int g = tid + i * 128;               // 4096 = 64 d2 * 64 x
        int d2 = g >> 6, xo = g & 63;
        op2[(size_t)d2 * HW + x0 + xo] = Ob[xo * OLD + d2];
    }
}

// ---------------------------------------------------------------------------
// GEMM3: out[ch][pos] = relu(BN(attn^T @ w3^T) + x)   grid (8, 16, NB)
// ---------------------------------------------------------------------------
__global__ __launch_bounds__(256, 2) void k_gemm3(
    const float* __restrict__ gamma, const float* __restrict__ beta,
    const float* __restrict__ mean, const float* __restrict__ var,
    const float* __restrict__ x, float* __restrict__ out) {
    extern __shared__ uint32_t smp[];
    int n = blockIdx.z, p0 = blockIdx.x * 128, c0 = blockIdx.y * 128;
    int tid = threadIdx.x, lane = tid & 31, warp = tid >> 5;
    int wm = warp & 3, wh = warp >> 2;
    int grp = lane >> 2, tg = lane & 3;
    float acc[2][8][4] = {};
    gemm_loop(smp, g_attn2 + (size_t)n * (MID / 2) * HW + p0,
              g_w3u + (size_t)blockIdx.y * (MID * 64), MID / 32,
              acc, wm, wh, lane, tid);
#pragma unroll
    for (int nt = 0; nt < 8; nt++) {
        int ch = c0 + wh * 64 + nt * 8 + 2 * tg;
        float i0 = gamma[ch] * rsqrtf(var[ch] + BN_EPS);
        float b0 = beta[ch] - mean[ch] * i0;
        float i1 = gamma[ch + 1] * rsqrtf(var[ch + 1] + BN_EPS);
        float b1 = beta[ch + 1] - mean[ch + 1] * i1;
#pragma unroll
        for (int mt = 0; mt < 2; mt++) {
            int p = p0 + wm * 32 + mt * 16 + grp;
            float* a4 = acc[mt][nt];
            size_t e0 = (size_t)n * CIN * HW + (size_t)ch * HW + p;
            size_t e1 = e0 + HW;
            out[e0]     = fmaxf(a4[0] * i0 + b0 + x[e0], 0.f);
            out[e1]     = fmaxf(a4[1] * i1 + b1 + x[e1], 0.f);
            out[e0 + 8] = fmaxf(a4[2] * i0 + b0 + x[e0 + 8], 0.f);
            out[e1 + 8] = fmaxf(a4[3] * i1 + b1 + x[e1 + 8], 0.f);
        }
    }
}

// ---------------------------------------------------------------------------
extern "C" void kernel_launch(void* const* d_in, const int* in_sizes, int n_in,
                              void* d_out, int out_size) {
    const float* x       = (const float*)d_in[0];
    const float* conv1_w = (const float*)d_in[1];
    const float* gamma1  = (const float*)d_in[2];
    const float* beta1   = (const float*)d_in[3];
    const float* mean1   = (const float*)d_in[4];
    const float* var1    = (const float*)d_in[5];
    const float* qk_w    = (const float*)d_in[6];
    const float* v_w     = (const float*)d_in[7];
    const float* pos_h   = (const float*)d_in[8];
    const float* pos_w   = (const float*)d_in[9];
    const float* conv3_w = (const float*)d_in[10];
    const float* gamma3  = (const float*)d_in[11];
    const float* beta3   = (const float*)d_in[12];
    const float* mean3   = (const float*)d_in[13];
    const float* var3    = (const float*)d_in[14];
    float* out = (float*)d_out;

    cudaFuncSetAttribute(k_gemm1, cudaFuncAttributeMaxDynamicSharedMemorySize,
                         GEMM_SMEM);
    cudaFuncSetAttribute(k_gemm2, cudaFuncAttributeMaxDynamicSharedMemorySize,
                         GEMM_SMEM);
    cudaFuncSetAttribute(k_gemm3, cudaFuncAttributeMaxDynamicSharedMemorySize,
                         GEMM_SMEM);

    uint32_t *p_x2, *p_w1, *p_wqkv, *p_w3;
    cudaGetSymbolAddress((void**)&p_x2, g_x2);
    cudaGetSymbolAddress((void**)&p_w1, g_w1u);
    cudaGetSymbolAddress((void**)&p_wqkv, g_wqkvu);
    cudaGetSymbolAddress((void**)&p_w3, g_w3u);

    dim3 blk256(256);
    // x -> bf16x2, vectorized: 4M uint4 / 256 = 16384 blocks
    k_roundx<<<16384, blk256>>>(x, (uint4*)p_x2);
    // all four weight repacks in one launch (1441792 u32 = 5632 blocks)
    k_repack_all<<<5632, blk256>>>(conv1_w, qk_w, v_w, conv3_w,
                                   p_w1, p_wqkv, p_w3);

    k_gemm1<<<dim3(8, 4, NB), blk256, GEMM_SMEM>>>(gamma1, beta1, mean1, var1);
    k_gemm2<<<dim3(8, 12, NB), blk256, GEMM_SMEM>>>(pos_h, pos_w);
    k_flash<<<dim3(16, 1, NB * NHEAD), dim3(128)>>>();
    k_gemm3<<<dim3(8, 16, NB), blk256, GEMM_SMEM>>>(gamma3, beta3, mean3, var3, x, out);
}